// round 17
// baseline (speedup 1.0000x reference)
#include <cuda_runtime.h>
#include <math.h>

#define B_    64
#define T_    512
#define EMB_  256
#define HD_   256
#define TAGS_ 11
#define NEGV  (-10000.0f)
#define GSTRIDE (256 * 64)   // gate stride in g_Gx elements

// ---------------- scratch (static device globals; no allocs) ----------------
__device__ __align__(16) float g_Gx[(long)2 * T_ * B_ * 1024]; // [dir][t][gate][unit][b]
__device__ __align__(16) float g_Hout[(long)2 * T_ * B_ * HD_]; // [dir][t][unit][b]
__device__ __align__(16) float g_feats[T_ * B_ * TAGS_];

// ---------------- packed f32x2 helpers ----------------
__device__ __forceinline__ void ffma2(unsigned long long& d,
                                      unsigned long long a,
                                      unsigned long long b) {
    asm("fma.rn.f32x2 %0, %1, %2, %0;" : "+l"(d) : "l"(a), "l"(b));
}
__device__ __forceinline__ float2 upk(unsigned long long v) {
    float2 f; asm("mov.b64 {%0, %1}, %2;" : "=f"(f.x), "=f"(f.y) : "l"(v)); return f;
}

// ---------------- fast activations ----------------
__device__ __forceinline__ float sigf(float x) {
    return __fdividef(1.f, 1.f + __expf(-x));
}
__device__ __forceinline__ float tanhfast(float x) {
    return fmaf(2.f, __fdividef(1.f, 1.f + __expf(-2.f * x)), -1.f);
}

// ---------------- cluster helpers ----------------
#define CLUSTER_ARRIVE() asm volatile("barrier.cluster.arrive.aligned;" ::: "memory")
#define CLUSTER_WAIT()   asm volatile("barrier.cluster.wait.aligned;" ::: "memory")

// =====================================================================
// K1: Gx = embed[sent] @ Wih.T + b, written as [dir][t][gate][unit][b].
// (R14 version, unchanged)
// =====================================================================
#define GX_STAGE_FLOATS (128 * 68)

__global__ void gx_kernel(const int* __restrict__ sent,
                          const float* __restrict__ embed,
                          const float* __restrict__ Wf, const float* __restrict__ bf,
                          const float* __restrict__ Wb, const float* __restrict__ bb)
{
    __shared__ __align__(16) float Sm[GX_STAGE_FLOATS];
    float* As = Sm;                // [row][k] stride 36
    float* Bs = Sm + 64 * 36;      // [col][k] stride 36
    __shared__ int toks[64];

    const int t     = blockIdx.x;
    const int dir   = blockIdx.y >> 3;
    const int gcol0 = (blockIdx.y & 7) * 128;
    const float* __restrict__ W    = dir ? Wb : Wf;
    const float* __restrict__ bias = dir ? bb : bf;

    const int tid = threadIdx.x;
    if (tid < 64) toks[tid] = sent[tid * T_ + t];
    __syncthreads();

    const int rowg = tid & 7;
    const int colg = tid >> 3;

    unsigned long long acc[8][4];
#pragma unroll
    for (int i = 0; i < 8; i++)
#pragma unroll
        for (int j = 0; j < 4; j++) acc[i][j] = 0ull;

    for (int k0 = 0; k0 < EMB_; k0 += 32) {
#pragma unroll
        for (int i = 0; i < 2; i++) {
            int e = tid + i * 256, r = e >> 3, seg = e & 7;
            float4 va = *(const float4*)(embed + (long)toks[r] * EMB_ + k0 + seg * 4);
            *(float4*)&As[r * 36 + seg * 4] = va;
        }
#pragma unroll
        for (int i = 0; i < 4; i++) {
            int e = tid + i * 256, r = e >> 3, seg = e & 7;
            float4 vb = *(const float4*)(W + (long)(gcol0 + r) * EMB_ + k0 + seg * 4);
            *(float4*)&Bs[r * 36 + seg * 4] = vb;
        }
        __syncthreads();
#pragma unroll
        for (int k4 = 0; k4 < 8; k4++) {
            ulonglong2 bv[4];
#pragma unroll
            for (int j = 0; j < 4; j++)
                bv[j] = *(const ulonglong2*)&Bs[(colg * 4 + j) * 36 + k4 * 4];
#pragma unroll
            for (int i = 0; i < 8; i++) {
                ulonglong2 av = *(const ulonglong2*)&As[(rowg + 8 * i) * 36 + k4 * 4];
#pragma unroll
                for (int j = 0; j < 4; j++) {
                    ffma2(acc[i][j], av.x, bv[j].x);
                    ffma2(acc[i][j], av.y, bv[j].y);
                }
            }
        }
        __syncthreads();
    }
    __syncthreads();

    float* stage = Sm;
#pragma unroll
    for (int j = 0; j < 4; j++) {
        int colL = colg * 4 + j;
        float bsv = bias[gcol0 + colL];
#pragma unroll
        for (int i = 0; i < 8; i++) {
            float2 p = upk(acc[i][j]);
            stage[colL * 68 + rowg + 8 * i] = p.x + p.y + bsv;
        }
    }
    __syncthreads();

    const long tb = (long)dir * T_ + t;
#pragma unroll
    for (int i = 0; i < 8; i++) {
        int id   = tid + i * 256;
        int colL = id >> 4;
        int b4   = id & 15;
        int gcol = gcol0 + colL;
        long obase = ((tb * 4 + (gcol >> 8)) * 256 + (gcol & 255)) * 64;
        float4 v = *(float4*)&stage[colL * 68 + b4 * 4];
        *(float4*)(g_Gx + obase + b4 * 4) = v;
    }
}

// =====================================================================
// K2: persistent BiLSTM via 8-CTA clusters + DSMEM exchange.
// Grid 128 CTAs x 256 threads; cluster = (dir, bg 8-batch group);
// rank (0..7) = 32-unit group. thread: b_loc = tid&7, uq = tid>>3.
// Per step: pull peers' h slots (ld.shared::cluster), dot, gates,
// publish to local slot, barrier.cluster (Gx prefetch between arrive/wait).
// smem floats: Whh 128x260 | hsm 8x260 | hslot 2x256  = 143,488 B
// =====================================================================
#define WST     260
#define SM_W    0
#define SM_HSM  (128 * WST)            // 33280
#define SM_SLOT (SM_HSM + 8 * WST)     // 35360
#define LSTM_SMEM ((SM_SLOT + 512) * 4)  // 143,488 B

__global__ void __launch_bounds__(256, 1) __cluster_dims__(8, 1, 1)
lstm_kernel(const float* __restrict__ Whh_f, const float* __restrict__ Whh_b,
            const float* __restrict__ h0f, const float* __restrict__ c0f,
            const float* __restrict__ h0b, const float* __restrict__ c0b,
            const float* __restrict__ mask)
{
    extern __shared__ __align__(16) float sm[];
    float* Whs   = sm + SM_W;     // [g*32+uu][k] stride WST
    float* hsm   = sm + SM_HSM;   // [b_loc][k]   stride WST
    float* hslot = sm + SM_SLOT;  // [p][b_loc*32 + uu]

    const int bx   = blockIdx.x;
    const int cid  = bx >> 3;           // cluster id 0..15
    const int rank = bx & 7;            // unit group 0..7
    const int dir  = cid >> 3;
    const int bg   = cid & 7;           // 8 batches each
    const int tid  = threadIdx.x;
    const int b_loc = tid & 7;
    const int uq    = tid >> 3;         // 0..31
    const int unit = rank * 32 + uq;
    const int b    = bg * 8 + b_loc;

    const float* __restrict__ Whh = dir ? Whh_b : Whh_f;
    const float* __restrict__ h0  = dir ? h0b : h0f;
    const float* __restrict__ c0  = dir ? c0b : c0f;
    float* HoutD = g_Hout + (long)dir * T_ * 64 * 256;   // [t][unit][b]

    const unsigned slot_u32 =
        (unsigned)__cvta_generic_to_shared(hslot);

    float c = c0[b * HD_ + unit];
    float h = h0[b * HD_ + unit];

    // publish h0 to slot 0, arrive; heavy preloads overlap peers' publish
    hslot[0 * 256 + b_loc * 32 + uq] = h;
    CLUSTER_ARRIVE();

    // preload weight slice: row r = g*32+uu  <-  Whh[g*256 + rank*32 + uu][k]
#pragma unroll
    for (int i = 0; i < 32; i++) {
        int f  = tid + i * 256;       // float4 idx 0..8191
        int r  = f >> 6;              // 0..127
        int k4 = f & 63;
        int grow = (r >> 5) * 256 + rank * 32 + (r & 31);
        *(float4*)&Whs[r * WST + k4 * 4] =
            *(const float4*)(Whh + (long)grow * HD_ + k4 * 4);
    }

    const float* w0p = &Whs[(0 * 32 + uq) * WST];
    const float* w1p = &Whs[(1 * 32 + uq) * WST];
    const float* w2p = &Whs[(2 * 32 + uq) * WST];
    const float* w3p = &Whs[(3 * 32 + uq) * WST];
    const float* hrow = &hsm[b_loc * WST];

    // prefetch Gx + mask for step 0
    const int t0 = dir ? (T_ - 1) : 0;
    const float* gx0 = g_Gx + (((long)dir * T_ + t0) * 4 * 256 + unit) * 64 + b;
    float ga0 = __ldg(gx0);
    float ga1 = __ldg(gx0 + GSTRIDE);
    float ga2 = __ldg(gx0 + 2 * GSTRIDE);
    float ga3 = __ldg(gx0 + 3 * GSTRIDE);
    float mt  = __ldg(mask + t0 * B_ + b);

    CLUSTER_WAIT();

    for (int s = 0; s < T_; s++) {
        const int t = dir ? (T_ - 1 - s) : s;
        const int p = s & 1;

        // ---- pull peers' h slot[p] into hsm via DSMEM ----
#pragma unroll
        for (int i = 0; i < 2; i++) {
            int e   = tid + i * 256;        // 0..511 float4 units
            int r   = e >> 6;               // peer rank 0..7
            int rem = e & 63;
            int bl  = rem >> 3;
            int u4  = rem & 7;
            unsigned laddr = slot_u32 + (unsigned)((p * 256 + bl * 32 + u4 * 4) * 4);
            unsigned raddr;
            asm("mapa.shared::cluster.u32 %0, %1, %2;"
                : "=r"(raddr) : "r"(laddr), "r"(r));
            float4 v;
            asm volatile("ld.shared::cluster.v4.f32 {%0, %1, %2, %3}, [%4];"
                : "=f"(v.x), "=f"(v.y), "=f"(v.z), "=f"(v.w) : "r"(raddr));
            *(float4*)&hsm[bl * WST + r * 32 + u4 * 4] = v;
        }
        __syncthreads();

        // ---- recurrent dot: 4 gates, K=256 ----
        unsigned long long a0p = 0ull, a1p = 0ull, a2p = 0ull, a3p = 0ull;
#pragma unroll 8
        for (int kk = 0; kk < 64; kk++) {
            ulonglong2 hv = *(const ulonglong2*)&hrow[kk * 4];
            ulonglong2 w0 = *(const ulonglong2*)&w0p[kk * 4];
            ulonglong2 w1 = *(const ulonglong2*)&w1p[kk * 4];
            ulonglong2 w2 = *(const ulonglong2*)&w2p[kk * 4];
            ulonglong2 w3 = *(const ulonglong2*)&w3p[kk * 4];
            ffma2(a0p, hv.x, w0.x); ffma2(a0p, hv.y, w0.y);
            ffma2(a1p, hv.x, w1.x); ffma2(a1p, hv.y, w1.y);
            ffma2(a2p, hv.x, w2.x); ffma2(a2p, hv.y, w2.y);
            ffma2(a3p, hv.x, w3.x); ffma2(a3p, hv.y, w3.y);
        }

        float2 q0 = upk(a0p), q1 = upk(a1p), q2 = upk(a2p), q3 = upk(a3p);
        float a0 = ga0 + q0.x + q0.y;
        float a1 = ga1 + q1.x + q1.y;
        float a2 = ga2 + q2.x + q2.y;
        float a3 = ga3 + q3.x + q3.y;

        float si = sigf(a0);
        float sf = sigf(a1);
        float tg = tanhfast(a2);
        float so = sigf(a3);
        float cn = sf * c + si * tg;
        float hn = so * tanhfast(cn);
        h = mt * hn + (1.f - mt) * h;
        c = mt * cn + (1.f - mt) * c;

        // publish to local slot[1-p]; arrive releases it cluster-wide
        hslot[(1 - p) * 256 + b_loc * 32 + uq] = h;
        CLUSTER_ARRIVE();

        // off-chain work between arrive and wait
        HoutD[((long)t * 256 + unit) * 64 + b] = h;
        if (s + 1 < T_) {
            const int tn = dir ? (T_ - 2 - s) : (s + 1);
            const float* gx = g_Gx + (((long)dir * T_ + tn) * 4 * 256 + unit) * 64 + b;
            ga0 = __ldg(gx);
            ga1 = __ldg(gx + GSTRIDE);
            ga2 = __ldg(gx + 2 * GSTRIDE);
            ga3 = __ldg(gx + 3 * GSTRIDE);
            mt  = __ldg(mask + tn * B_ + b);
        }

        CLUSTER_WAIT();
    }
}

// =====================================================================
// K3: feats[t][b][j] = (sum_k (h[k]*m) * Wtag[j][k] + btag[j]) * m
// =====================================================================
__global__ void feats_kernel(const float* __restrict__ Wtag,
                             const float* __restrict__ btag,
                             const float* __restrict__ mask)
{
    __shared__ float Ws[TAGS_ * 512];
    __shared__ float bts[TAGS_];
    const int t   = blockIdx.x;
    const int tid = threadIdx.x;
    for (int i = tid; i < TAGS_ * 512; i += 256) Ws[i] = Wtag[i];
    if (tid < TAGS_) bts[tid] = btag[tid];
    __syncthreads();

    const int w    = tid >> 5;
    const int lane = tid & 31;
    const float* Hf = g_Hout + ((long)t * 256) * 64;
    const float* Hb = g_Hout + ((long)T_ * 256 + (long)t * 256) * 64;
    for (int b = w; b < B_; b += 8) {
        float mt = mask[t * B_ + b];
        float acc[TAGS_];
#pragma unroll
        for (int j = 0; j < TAGS_; j++) acc[j] = 0.f;
        for (int k = lane; k < HD_; k += 32) {
            float hv  = Hf[k * 64 + b] * mt;
            float hv2 = Hb[k * 64 + b] * mt;
#pragma unroll
            for (int j = 0; j < TAGS_; j++) {
                acc[j] = fmaf(hv,  Ws[j * 512 + k],       acc[j]);
                acc[j] = fmaf(hv2, Ws[j * 512 + HD_ + k], acc[j]);
            }
        }
#pragma unroll
        for (int j = 0; j < TAGS_; j++)
#pragma unroll
            for (int off = 16; off > 0; off >>= 1)
                acc[j] += __shfl_xor_sync(0xffffffffu, acc[j], off);
        if (lane < TAGS_)
            g_feats[(t * B_ + b) * TAGS_ + lane] = (acc[lane] + bts[lane]) * mt;
    }
}

// =====================================================================
// K4: Viterbi. 1 CTA/batch. fmax-tree chain, off-chain argmax.
// =====================================================================
__global__ void viterbi_kernel(const float* __restrict__ trans,
                               const float* __restrict__ mask,
                               float* __restrict__ out, int out_size)
{
    __shared__ float fsh[T_ * TAGS_];
    __shared__ float msh[T_];
    __shared__ unsigned char ptrs[T_ * TAGS_];
    __shared__ float trs[TAGS_ * TAGS_];
    const int bb  = blockIdx.x;
    const int tid = threadIdx.x;   // 128

    for (int i = tid; i < T_ * TAGS_; i += 128) {
        int t = i / TAGS_, j = i % TAGS_;
        fsh[i] = g_feats[(t * B_ + bb) * TAGS_ + j];
    }
    for (int i = tid; i < T_; i += 128) msh[i] = mask[i * B_ + bb];
    for (int i = tid; i < TAGS_ * TAGS_; i += 128) trs[i] = trans[i];
    __syncthreads();
    if (tid >= 32) return;

    const int j  = tid;
    const int jc = (j < TAGS_) ? j : 0;
    float trow[TAGS_];
#pragma unroll
    for (int q = 0; q < TAGS_; q++) trow[q] = trs[jc * TAGS_ + q];

    float s[TAGS_];
#pragma unroll
    for (int q = 0; q < TAGS_; q++) s[q] = (q == 9) ? 0.f : NEGV;   // START=9

    for (int t = 0; t < T_; t++) {
        float ft = fsh[t * TAGS_ + jc];
        float mt = msh[t];

        float v[TAGS_];
#pragma unroll
        for (int q = 0; q < TAGS_; q++) v[q] = s[q] + trow[q];

        float m0 = fmaxf(v[0], v[1]);
        float m1 = fmaxf(v[2], v[3]);
        float m2 = fmaxf(v[4], v[5]);
        float m3 = fmaxf(v[6], v[7]);
        float m4 = fmaxf(v[8], v[9]);
        float n0 = fmaxf(m0, m1);
        float n1 = fmaxf(m2, m3);
        float n2 = fmaxf(m4, v[10]);
        float best = fmaxf(fmaxf(n0, n1), n2);

        int arg = 10;
#pragma unroll
        for (int q = 9; q >= 0; q--) arg = (v[q] == best) ? q : arg;
        if (j < TAGS_) ptrs[t * TAGS_ + j] = (unsigned char)arg;

        float ns = best + ft;
        float sn = (mt > 0.f) ? ns : s[jc];
#pragma unroll
        for (int q = 0; q < TAGS_; q++)
            s[q] = __shfl_sync(0xffffffffu, sn, q);
    }

    float fv[TAGS_];
#pragma unroll
    for (int q = 0; q < TAGS_; q++) fv[q] = s[q] + trs[10 * TAGS_ + q];   // STOP=10
    float fb = fv[0];
#pragma unroll
    for (int q = 1; q < TAGS_; q++) fb = fmaxf(fb, fv[q]);
    int fbt = 10;
#pragma unroll
    for (int q = 9; q >= 0; q--) fbt = (fv[q] == fb) ? q : fbt;

    if (tid == 0) {
        if (out_size >= B_ * T_ + B_) out[B_ * T_ + bb] = fb;
        int cur = fbt;
        for (int t = T_ - 1; t >= 0; t--) {
            if (bb * T_ + t < out_size) out[bb * T_ + t] = (float)cur;
            cur = ptrs[t * TAGS_ + cur];
        }
    }
}

// =====================================================================
extern "C" void kernel_launch(void* const* d_in, const int* in_sizes, int n_in,
                              void* d_out, int out_size)
{
    const int*   sent  = (const int*)d_in[0];
    const float* mask  = (const float*)d_in[1];
    const float* embed = (const float*)d_in[2];
    const float* Wih_f = (const float*)d_in[3];
    const float* Whh_f = (const float*)d_in[4];
    const float* b_f   = (const float*)d_in[5];
    const float* Wih_b = (const float*)d_in[6];
    const float* Whh_b = (const float*)d_in[7];
    const float* b_b   = (const float*)d_in[8];
    const float* h0f   = (const float*)d_in[9];
    const float* c0f   = (const float*)d_in[10];
    const float* h0b   = (const float*)d_in[11];
    const float* c0b   = (const float*)d_in[12];
    const float* Wtag  = (const float*)d_in[13];
    const float* btag  = (const float*)d_in[14];
    const float* trans = (const float*)d_in[15];

    gx_kernel<<<dim3(T_, 16), 256>>>(sent, embed, Wih_f, b_f, Wih_b, b_b);

    cudaFuncSetAttribute(lstm_kernel, cudaFuncAttributeMaxDynamicSharedMemorySize, LSTM_SMEM);
    lstm_kernel<<<128, 256, LSTM_SMEM>>>(Whh_f, Whh_b, h0f, c0f, h0b, c0b, mask);

    feats_kernel<<<T_, 256>>>(Wtag, btag, mask);

    viterbi_kernel<<<B_, 128>>>(trans, mask, (float*)d_out, out_size);
}